// round 1
// baseline (speedup 1.0000x reference)
#include <cuda_runtime.h>

// Problem constants
static const int cB  = 2;
static const int cN  = 2065;   // 2048 + 16 + 1
static const int cNP = 2048;
static const int cNT = 16;
static const int cE  = 512;
static const int cH  = 8;
static const int cE3 = 1536;
#define SCALE_QK 0.125f
#define EPS_BAL  1e-6f

// Scratch (static device globals: allocation-free)
__device__ float g_qkv[(size_t)cB * cN * cE3];   // ~25.4 MB
__device__ float g_oh [(size_t)cB * cN * cE];    // ~8.5 MB, heads-merged layout (B,N,E)

// ---------------------------------------------------------------------------
// Generic GEMM + bias: C[M,Nc] = A[M,K] @ W[K,Nc] + bias[Nc]
// BM=BN=64, BK=16, 256 threads, 4x4 per thread. K % 16 == 0, Nc % 64 == 0.
// ---------------------------------------------------------------------------
__global__ void gemm_bias_kernel(const float* __restrict__ A,
                                 const float* __restrict__ W,
                                 const float* __restrict__ bias,
                                 float* __restrict__ C,
                                 int M, int Nc, int K) {
    __shared__ float As[16][68];   // [k][m]
    __shared__ float Ws[16][68];   // [k][n]
    const int t  = threadIdx.x;
    const int tx = t & 15, ty = t >> 4;
    const int m0 = blockIdx.y * 64, n0 = blockIdx.x * 64;

    float acc[4][4] = {};

    for (int k0 = 0; k0 < K; k0 += 16) {
        // A tile: 64 rows x 16 cols = 256 float4, one per thread
        {
            int r = t >> 2, c4 = t & 3;
            float4 v = make_float4(0.f, 0.f, 0.f, 0.f);
            int gr = m0 + r;
            if (gr < M)
                v = *reinterpret_cast<const float4*>(&A[(size_t)gr * K + k0 + c4 * 4]);
            As[c4 * 4 + 0][r] = v.x;
            As[c4 * 4 + 1][r] = v.y;
            As[c4 * 4 + 2][r] = v.z;
            As[c4 * 4 + 3][r] = v.w;
        }
        // W tile: 16 rows x 64 cols = 256 float4, one per thread
        {
            int r = t >> 4, c4 = t & 15;
            float4 v = *reinterpret_cast<const float4*>(&W[(size_t)(k0 + r) * Nc + n0 + c4 * 4]);
            *reinterpret_cast<float4*>(&Ws[r][c4 * 4]) = v;
        }
        __syncthreads();

        #pragma unroll
        for (int kk = 0; kk < 16; kk++) {
            float4 a = *reinterpret_cast<const float4*>(&As[kk][ty * 4]);
            float4 b = *reinterpret_cast<const float4*>(&Ws[kk][tx * 4]);
            float av[4] = {a.x, a.y, a.z, a.w};
            float bv[4] = {b.x, b.y, b.z, b.w};
            #pragma unroll
            for (int i = 0; i < 4; i++)
                #pragma unroll
                for (int j = 0; j < 4; j++)
                    acc[i][j] = fmaf(av[i], bv[j], acc[i][j]);
        }
        __syncthreads();
    }

    #pragma unroll
    for (int i = 0; i < 4; i++) {
        int gr = m0 + ty * 4 + i;
        if (gr >= M) continue;
        #pragma unroll
        for (int j = 0; j < 4; j++) {
            int gc = n0 + tx * 4 + j;
            C[(size_t)gr * Nc + gc] = acc[i][j] + bias[gc];
        }
    }
}

// ---------------------------------------------------------------------------
// QK^T per (b,h): A_raw[bh,n,m] = SCALE * sum_d q[n,d]*k[m,d]
// q rows at g_qkv[b*N*E3 + n*E3 + h*64 + d], k at +E offset.
// Block = 64x64 output tile, full K=64 in one smem load.
// ---------------------------------------------------------------------------
__global__ void qk_kernel(const float* __restrict__ qkv,
                          float* __restrict__ A_raw) {
    __shared__ float Qs[64][68];   // [d][n]
    __shared__ float Ks[64][68];   // [d][m]
    const int bh = blockIdx.z;
    const int b = bh >> 3, h = bh & 7;
    const int n0 = blockIdx.y * 64, m0 = blockIdx.x * 64;
    const float* qbase = qkv + (size_t)b * cN * cE3 + h * 64;
    const float* kbase = qbase + cE;
    const int t  = threadIdx.x;
    const int r = t >> 4, c4 = t & 15;

    #pragma unroll
    for (int i = 0; i < 4; i++) {
        int row = r + i * 16;
        float4 qv = make_float4(0.f, 0.f, 0.f, 0.f);
        float4 kv = make_float4(0.f, 0.f, 0.f, 0.f);
        if (n0 + row < cN)
            qv = *reinterpret_cast<const float4*>(&qbase[(size_t)(n0 + row) * cE3 + c4 * 4]);
        if (m0 + row < cN)
            kv = *reinterpret_cast<const float4*>(&kbase[(size_t)(m0 + row) * cE3 + c4 * 4]);
        Qs[c4 * 4 + 0][row] = qv.x; Qs[c4 * 4 + 1][row] = qv.y;
        Qs[c4 * 4 + 2][row] = qv.z; Qs[c4 * 4 + 3][row] = qv.w;
        Ks[c4 * 4 + 0][row] = kv.x; Ks[c4 * 4 + 1][row] = kv.y;
        Ks[c4 * 4 + 2][row] = kv.z; Ks[c4 * 4 + 3][row] = kv.w;
    }
    __syncthreads();

    const int tx = t & 15, ty = t >> 4;
    float acc[4][4] = {};
    #pragma unroll
    for (int d = 0; d < 64; d++) {
        float4 a = *reinterpret_cast<const float4*>(&Qs[d][ty * 4]);
        float4 bq = *reinterpret_cast<const float4*>(&Ks[d][tx * 4]);
        float av[4] = {a.x, a.y, a.z, a.w};
        float bv[4] = {bq.x, bq.y, bq.z, bq.w};
        #pragma unroll
        for (int i = 0; i < 4; i++)
            #pragma unroll
            for (int j = 0; j < 4; j++)
                acc[i][j] = fmaf(av[i], bv[j], acc[i][j]);
    }

    const size_t base = (size_t)bh * cN * cN;
    #pragma unroll
    for (int i = 0; i < 4; i++) {
        int gr = n0 + ty * 4 + i;
        if (gr >= cN) continue;
        #pragma unroll
        for (int j = 0; j < 4; j++) {
            int gc = m0 + tx * 4 + j;
            if (gc >= cN) continue;
            A_raw[base + (size_t)gr * cN + gc] = acc[i][j] * SCALE_QK;
        }
    }
}

// ---------------------------------------------------------------------------
// Balanced attention: one block per (b,h,n) row.
// ---------------------------------------------------------------------------
__inline__ __device__ float warpSum(float v) {
    #pragma unroll
    for (int o = 16; o > 0; o >>= 1) v += __shfl_down_sync(0xffffffffu, v, o);
    return v;
}

__global__ void balanced_kernel(const float* __restrict__ A_raw,
                                float* __restrict__ A) {
    __shared__ float srow[cN];
    __shared__ float red[4][8];
    __shared__ float fac[3];
    const size_t row = blockIdx.x;
    const float* src = A_raw + row * cN;
    float* dst = A + row * cN;
    const int t = threadIdx.x;

    float sum_p = 0.f, se_p = 0.f, sum_t = 0.f, se_t = 0.f;
    for (int i = t; i < cN; i += 256) {
        float v = src[i];
        srow[i] = v;
        float e = __expf(v);
        if (i < cNP)            { sum_p += v; se_p += e; }
        else if (i < cNP + cNT) { sum_t += v; se_t += e; }
    }
    sum_p = warpSum(sum_p); se_p = warpSum(se_p);
    sum_t = warpSum(sum_t); se_t = warpSum(se_t);
    const int lane = t & 31, w = t >> 5;
    if (lane == 0) { red[0][w] = sum_p; red[1][w] = se_p; red[2][w] = sum_t; red[3][w] = se_t; }
    __syncthreads();
    if (t == 0) {
        float SP = 0.f, SEP = 0.f, ST = 0.f, SET = 0.f;
        #pragma unroll
        for (int i = 0; i < 8; i++) { SP += red[0][i]; SEP += red[1][i]; ST += red[2][i]; SET += red[3][i]; }
        float ac = srow[cNP + cNT];           // single cls logit (max over 1 elem)
        float ep = __expf(SP / (float)cNP);
        float et = __expf(ST / (float)cNT);
        float ec = __expf(ac);
        float s  = ep + et + ec;
        fac[0] = (ep / s) / (SEP + EPS_BAL);
        fac[1] = (et / s) / (SET + EPS_BAL);
        fac[2] = (ec / s) / (ec  + EPS_BAL);
    }
    __syncthreads();
    const float f0 = fac[0], f1 = fac[1], f2 = fac[2];
    for (int i = t; i < cN; i += 256) {
        float f = (i < cNP) ? f0 : (i < cNP + cNT ? f1 : f2);
        dst[i] = __expf(srow[i]) * f;
    }
}

// ---------------------------------------------------------------------------
// AV per (b,h): OH[b,n, h*64+d] = sum_m A[bh,n,m] * v[m,d]
// v rows at g_qkv[b*N*E3 + m*E3 + 2E + h*64 + d].
// ---------------------------------------------------------------------------
__global__ void av_kernel(const float* __restrict__ A,
                          const float* __restrict__ qkv,
                          float* __restrict__ OH) {
    __shared__ float Ats[64][68];  // [m][n]
    __shared__ float Vs [64][68];  // [m][d]
    const int bh = blockIdx.z;
    const int b = bh >> 3, h = bh & 7;
    const int n0 = blockIdx.x * 64;
    const float* Ab    = A + (size_t)bh * cN * cN;
    const float* vbase = qkv + (size_t)b * cN * cE3 + 2 * cE + h * 64;
    const int t  = threadIdx.x;
    const int tx = t & 15, ty = t >> 4;

    float acc[4][4] = {};

    for (int m0 = 0; m0 < cN; m0 += 64) {
        // A tile (scalar loads: odd row stride)
        for (int l = t; l < 4096; l += 256) {
            int rr = l >> 6, cc = l & 63;
            float v = 0.f;
            if (n0 + rr < cN && m0 + cc < cN)
                v = Ab[(size_t)(n0 + rr) * cN + m0 + cc];
            Ats[cc][rr] = v;
        }
        // V tile
        {
            int r = t >> 4, c4 = t & 15;
            #pragma unroll
            for (int i = 0; i < 4; i++) {
                int row = r + i * 16;
                float4 v = make_float4(0.f, 0.f, 0.f, 0.f);
                if (m0 + row < cN)
                    v = *reinterpret_cast<const float4*>(&vbase[(size_t)(m0 + row) * cE3 + c4 * 4]);
                *reinterpret_cast<float4*>(&Vs[row][c4 * 4]) = v;
            }
        }
        __syncthreads();

        #pragma unroll
        for (int kk = 0; kk < 64; kk++) {
            float4 a = *reinterpret_cast<const float4*>(&Ats[kk][ty * 4]);
            float4 b4 = *reinterpret_cast<const float4*>(&Vs[kk][tx * 4]);
            float av[4] = {a.x, a.y, a.z, a.w};
            float bv[4] = {b4.x, b4.y, b4.z, b4.w};
            #pragma unroll
            for (int i = 0; i < 4; i++)
                #pragma unroll
                for (int j = 0; j < 4; j++)
                    acc[i][j] = fmaf(av[i], bv[j], acc[i][j]);
        }
        __syncthreads();
    }

    #pragma unroll
    for (int i = 0; i < 4; i++) {
        int n = n0 + ty * 4 + i;
        if (n >= cN) continue;
        #pragma unroll
        for (int j = 0; j < 4; j++) {
            OH[(size_t)(b * cN + n) * cE + h * 64 + tx * 4 + j] = acc[i][j];
        }
    }
}

// ---------------------------------------------------------------------------
extern "C" void kernel_launch(void* const* d_in, const int* in_sizes, int n_in,
                              void* d_out, int out_size) {
    const float* x     = (const float*)d_in[0];
    const float* w_qkv = (const float*)d_in[1];
    const float* b_qkv = (const float*)d_in[2];
    const float* w_out = (const float*)d_in[3];
    const float* b_out = (const float*)d_in[4];

    float* out   = (float*)d_out;
    float* A     = out + (size_t)cB * cN * cE;
    float* A_raw = A   + (size_t)cB * cH * cN * cN;

    float* qkv = nullptr;
    float* oh  = nullptr;
    cudaGetSymbolAddress((void**)&qkv, g_qkv);
    cudaGetSymbolAddress((void**)&oh,  g_oh);

    const int M = cB * cN;  // 4130

    // 1) QKV projection: (4130 x 512) @ (512 x 1536) + bias
    {
        dim3 grid(cE3 / 64, (M + 63) / 64);
        gemm_bias_kernel<<<grid, 256>>>(x, w_qkv, b_qkv, qkv, M, cE3, cE);
    }
    // 2) A_raw = scale * Q K^T  (per b,h)
    {
        dim3 grid((cN + 63) / 64, (cN + 63) / 64, cB * cH);
        qk_kernel<<<grid, 256>>>(qkv, A_raw);
    }
    // 3) Balanced attention rows
    {
        balanced_kernel<<<cB * cH * cN, 256>>>(A_raw, A);
    }
    // 4) OH = A @ V (per b,h), written heads-merged
    {
        dim3 grid((cN + 63) / 64, 1, cB * cH);
        av_kernel<<<grid, 256>>>(A, qkv, oh);
    }
    // 5) out = OH @ w_out + b_out
    {
        dim3 grid(cE / 64, (M + 63) / 64);
        gemm_bias_kernel<<<grid, 256>>>(oh, w_out, b_out, out, M, cE, cE);
    }
}